// round 14
// baseline (speedup 1.0000x reference)
#include <cuda_runtime.h>
#include <cuda_fp16.h>
#include <cstdint>

// ---------------------------------------------------------------- shapes
#define B_  8
#define S_  96
#define D_  768
#define M_  (B_ * S_ * S_)   // 73728 rows
#define K_  768
#define N1_ 768
#define N2_ 256

// GEMM tiling (mma.sync path, base ISA only)
#define BKg 32               // k per stage
#define NTg (K_ / BKg)       // 24 k-tiles
#define LDAB 80              // bytes per smem row (32 fp16 = 64B + 16B pad)
#define NSTAGE 4
// GEMM1: CTA 128x128, warp 64x32 (2M x 4N)
#define BM1 128
#define BN1 128
#define T1_A 0               // 128 rows * 80B = 10240
#define T1_W 10240
#define STG1 20480
#define SMEM_G1 (NSTAGE * STG1)    // 81920
// GEMM2: CTA 64x256, warp 32x64 (2M x 4N); full N in CTA -> fused RMS
#define BM2 64
#define BN2 256
#define T2_A 0               // 64 rows * 80B = 5120
#define T2_W 5120            // 256 rows * 80B = 20480
#define STG2 25600
#define SMEM_G2 (NSTAGE * STG2)    // 102400
// gather tiling
#define LSL 4                // l-slabs per block
#define KSP 4                // k-range splits

// ---------------- scratch (static device globals; no allocations) ----------
// RULE: these symbols are referenced ONLY from device code, never passed as
// kernel arguments from host (host-side shadow address bug, rounds 7 & 10).
static __device__ __half g_Yh[(size_t)M_ * N1_];       // GEMM1 out (pre-norm), fp16
static __device__ float  g_rsum[M_];                   // per-row sum of squares
static __device__ float  g_rfac[M_];                   // rsqrt factors
static __device__ __half g_A[(size_t)M_ * K_];         // gather out, fp16
static __device__ __half g_W1T[(size_t)N1_ * K_];      // W^T, k-contiguous, fp16
static __device__ __half g_W2T[(size_t)N2_ * K_];

// ---------------------------------------------------------------- helpers
__device__ __forceinline__ uint32_t smem_u32(const void* p) {
    uint32_t a;
    asm("{ .reg .u64 t; cvta.to.shared.u64 t, %1; cvt.u32.u64 %0, t; }" : "=r"(a) : "l"(p));
    return a;
}

__device__ __forceinline__ void cp16(uint32_t s, const void* g) {
    asm volatile("cp.async.cg.shared.global [%0], [%1], 16;" :: "r"(s), "l"(g));
}
#define CP_COMMIT() asm volatile("cp.async.commit_group;" ::: "memory")
#define CP_WAIT2()  asm volatile("cp.async.wait_group 2;" ::: "memory")
#define CP_WAIT1()  asm volatile("cp.async.wait_group 1;" ::: "memory")
#define CP_WAIT0()  asm volatile("cp.async.wait_group 0;" ::: "memory")

#define LDSM4(r, addr) \
    asm volatile("ldmatrix.sync.aligned.m8n8.x4.shared.b16 {%0,%1,%2,%3}, [%4];" \
        : "=r"((r)[0]), "=r"((r)[1]), "=r"((r)[2]), "=r"((r)[3]) : "r"(addr))

#define MMA_F16(Cv, Av, Bv) asm volatile( \
    "mma.sync.aligned.m16n8k16.row.col.f32.f16.f16.f32 " \
    "{%0,%1,%2,%3}, {%4,%5,%6,%7}, {%8,%9}, {%0,%1,%2,%3};\n" \
    : "+f"((Cv)[0]), "+f"((Cv)[1]), "+f"((Cv)[2]), "+f"((Cv)[3]) \
    : "r"((Av)[0]), "r"((Av)[1]), "r"((Av)[2]), "r"((Av)[3]), \
      "r"((Bv)[0]), "r"((Bv)[1]))

// ---------------- kernel 1: coalesced W -> W^T fp16 transpose ---------------
// Destination selected INSIDE device code (which=0 -> g_W1T, 1 -> g_W2T).
__global__ void trans_kernel(const float* __restrict__ W, int which, int N)
{
    __half* __restrict__ WT = which ? g_W2T : g_W1T;
    __shared__ float tile[32][33];
    const int n0 = blockIdx.x * 32, k0 = blockIdx.y * 32;
    const int tx = threadIdx.x, ty = threadIdx.y;
#pragma unroll
    for (int r = 0; r < 4; r++)
        tile[ty + 8 * r][tx] = W[(size_t)(k0 + ty + 8 * r) * N + n0 + tx];
    __syncthreads();
#pragma unroll
    for (int r = 0; r < 4; r++)
        WT[(size_t)(n0 + ty + 8 * r) * K_ + k0 + tx] = __float2half(tile[tx][ty + 8 * r]);
}

// ---------------- kernel 2: 4-slab register-tiled gather stencil ------------
__device__ __forceinline__ void fma4(float4& r, float s, const float4 v) {
    r.x += s * v.x; r.y += s * v.y; r.z += s * v.z; r.w += s * v.w;
}

__device__ __forceinline__ float4 loadrow(const float* __restrict__ hf, int src, int t,
                                          int use_norm, const float4 g4)
{
    float4 v;
    if (hf) {
        v = ((const float4*)(hf + (size_t)src * D_))[t];
    } else {
        uint2 u = *((const uint2*)(g_Yh + (size_t)src * D_) + t);
        __half2 a = *(__half2*)&u.x;
        __half2 b = *(__half2*)&u.y;
        v.x = __half2float(a.x); v.y = __half2float(a.y);
        v.z = __half2float(b.x); v.w = __half2float(b.y);
    }
    if (use_norm) {
        const float r = g_rfac[src];
        v.x = fmaxf(g4.x * v.x * r, 0.f);
        v.y = fmaxf(g4.y * v.y * r, 0.f);
        v.z = fmaxf(g4.z * v.z * r, 0.f);
        v.w = fmaxf(g4.w * v.w * r, 0.f);
    }
    return v;
}

// One block = 4 adjacent l-slabs x one quarter of the k-range. Each slab has a
// prev/cur/nxt register rotation (own rows read once); interior up/down
// neighbors come from the adjacent rotation's `cur` register; only the two
// boundary slabs (l0-1, l0+4) are loaded per k-step.
__global__ void gather_kernel(const float* __restrict__ table,
                              const float* __restrict__ a_simi,
                              const float* __restrict__ t_simi,
                              const float* __restrict__ adj,
                              int use_norm, const float* __restrict__ gw)
{
    const int kq  = blockIdx.x & (KSP - 1);
    const int bl4 = blockIdx.x / KSP;                  // b*(S/LSL) + l0/LSL
    const int b  = bl4 / (S_ / LSL);
    const int l0 = (bl4 % (S_ / LSL)) * LSL;
    const int t = threadIdx.x;                         // 0..191 (float4 over D)
    const int k0 = kq * (S_ / KSP);
    const int k1 = k0 + (S_ / KSP);

    float4 g4 = make_float4(1.f, 1.f, 1.f, 1.f);
    if (use_norm) g4 = ((const float4*)gw)[t];

    const float4 zero4 = make_float4(0.f, 0.f, 0.f, 0.f);

    int   base[LSL];
    float au[LSL], ad[LSL];
    float4 diag[LSL], prev[LSL], cur[LSL], nxt[LSL];
#pragma unroll
    for (int j = 0; j < LSL; j++) {
        const int l = l0 + j;
        base[j] = (b * S_ + l) * S_;
        au[j] = (l > 0)      ? a_simi[b * S_ + l - 1] : 0.f;
        ad[j] = (l < S_ - 1) ? a_simi[b * S_ + l + 1] : 0.f;
        diag[j] = loadrow(table, base[j] + l, t, use_norm, g4);
        prev[j] = (k0 > 0) ? loadrow(table, base[j] + k0 - 1, t, use_norm, g4) : zero4;
        cur[j]  = loadrow(table, base[j] + k0, t, use_norm, g4);
        nxt[j]  = loadrow(table, base[j] + k0 + 1, t, use_norm, g4);
    }

    for (int k = k0; k < k1; k++) {
        // external boundary neighbors (slabs l0-1 and l0+LSL)
        const float4 up = (l0 > 0)         ? loadrow(table, base[0] - S_ + k, t, use_norm, g4) : zero4;
        const float4 dn = (l0 + LSL < S_)  ? loadrow(table, base[LSL - 1] + S_ + k, t, use_norm, g4) : zero4;
        const float tl = (k > 0)      ? t_simi[b * S_ + k - 1] : 0.f;
        const float tr = (k < S_ - 1) ? t_simi[b * S_ + k + 1] : 0.f;

#pragma unroll
        for (int j = 0; j < LSL; j++) {
            const int idx = base[j] + k;
            const float adjv = adj[idx];
            float4 r;
            r.x = 2.f * cur[j].x + adjv * diag[j].x;
            r.y = 2.f * cur[j].y + adjv * diag[j].y;
            r.z = 2.f * cur[j].z + adjv * diag[j].z;
            r.w = 2.f * cur[j].w + adjv * diag[j].w;
            if (k > 0)      fma4(r, tl, prev[j]);
            if (k < S_ - 1) fma4(r, tr, nxt[j]);
            fma4(r, au[j], (j == 0)       ? up : cur[j - 1]);
            fma4(r, ad[j], (j == LSL - 1) ? dn : cur[j + 1]);

            __half2 v01, v23;
            v01.x = __float2half(r.x); v01.y = __float2half(r.y);
            v23.x = __float2half(r.z); v23.y = __float2half(r.w);
            __half2* pa = (__half2*)(g_A + (size_t)idx * D_) + 2 * t;
            pa[0] = v01;
            pa[1] = v23;
            if (!use_norm && t == 0) g_rsum[idx] = 0.f;
        }
        // rotate all slabs
#pragma unroll
        for (int j = 0; j < LSL; j++) {
            prev[j] = cur[j]; cur[j] = nxt[j];
            nxt[j] = (k + 2 < S_) ? loadrow(table, base[j] + k + 2, t, use_norm, g4) : zero4;
        }
    }
}

// ---------------- kernel 3: rfac = rsqrt(rsum/D + eps) ----------------------
__global__ void rfac_kernel()
{
    int i = blockIdx.x * blockDim.x + threadIdx.x;
    if (i < M_) g_rfac[i] = rsqrtf(g_rsum[i] * (1.f / (float)N1_) + 1e-12f);
}

// ---------------- kernel 4: GEMM1  Yh = fp16(A@W1^T + b1), +rsum ------------
// CTA 128x128x32, 256 thr (8 warps 2Mx4N, warp 64x32), 4-stage cp.async,
// single barrier per k-tile, 2 CTAs/SM.
__global__ void __launch_bounds__(256, 2)
gemm1_kernel(const float* __restrict__ bias)
{
    extern __shared__ __align__(128) char smem[];
    const int tid  = threadIdx.x;
    const int wid  = tid >> 5;
    const int lane = tid & 31;
    const int wm   = wid & 1;            // 0..1, 64 rows each
    const int wn   = wid >> 1;           // 0..3, 32 cols each
    const int m0 = blockIdx.y * BM1;
    const int n0 = blockIdx.x * BN1;
    const uint32_t sb = smem_u32(smem);

    const int lrow = tid >> 2;           // 0..63
    const int lch  = tid & 3;
    const uint32_t sRow = (uint32_t)(lrow * LDAB + lch * 16);

    uint32_t aOff[4], wOff[2];
#pragma unroll
    for (int mi = 0; mi < 4; mi++)
        aOff[mi] = (uint32_t)((wm * 64 + mi * 16 + (lane & 15)) * LDAB) + T1_A;
#pragma unroll
    for (int nj = 0; nj < 2; nj++)
        wOff[nj] = (uint32_t)((wn * 32 + nj * 16 + (lane & 15)) * LDAB) + T1_W;

    float c[4][4][4] = {};

#define LOAD_STAGE1(st, kt_) do {                                              \
        uint32_t s = sb + (uint32_t)(st) * STG1 + sRow;                        \
        _Pragma("unroll")                                                      \
        for (int i_ = 0; i_ < 2; i_++) {                                       \
            size_t gA_ = (size_t)(m0 + lrow + i_ * 64) * K_ + (kt_) + lch * 8; \
            cp16(s + T1_A + (uint32_t)(i_ * 64 * LDAB), g_A + gA_);            \
            size_t gW_ = (size_t)(n0 + lrow + i_ * 64) * K_ + (kt_) + lch * 8; \
            cp16(s + T1_W + (uint32_t)(i_ * 64 * LDAB), g_W1T + gW_);          \
        }                                                                      \
        CP_COMMIT();                                                           \
    } while (0)

    LOAD_STAGE1(0, 0);
    LOAD_STAGE1(1, BKg);
    LOAD_STAGE1(2, 2 * BKg);

    for (int t = 0; t < NTg; t++) {
        if (t < NTg - 2)       CP_WAIT2();
        else if (t == NTg - 2) CP_WAIT1();
        else                   CP_WAIT0();
        __syncthreads();
        if (t + 3 < NTg) LOAD_STAGE1((t + 3) % NSTAGE, (t + 3) * BKg);

        const uint32_t bufb = sb + (uint32_t)(t % NSTAGE) * STG1;
#pragma unroll
        for (int ks = 0; ks < 2; ks++) {
            const uint32_t kb = bufb + (uint32_t)(ks * 32 + (lane >> 4) * 16);
            uint32_t aw[4][4], bw[2][4];
#pragma unroll
            for (int mi = 0; mi < 4; mi++) LDSM4(aw[mi], kb + aOff[mi]);
#pragma unroll
            for (int nj = 0; nj < 2; nj++) LDSM4(bw[nj], kb + wOff[nj]);
#pragma unroll
            for (int mi = 0; mi < 4; mi++)
#pragma unroll
                for (int nj = 0; nj < 2; nj++) {
                    uint32_t f0[2] = {bw[nj][0], bw[nj][2]};
                    uint32_t f1[2] = {bw[nj][1], bw[nj][3]};
                    MMA_F16(c[mi][2 * nj],     aw[mi], f0);
                    MMA_F16(c[mi][2 * nj + 1], aw[mi], f1);
                }
        }
    }
#undef LOAD_STAGE1

    // epilogue: + bias, fp16 store, per-row sumsq via atomics
#pragma unroll
    for (int mi = 0; mi < 4; mi++) {
        const int row = m0 + wm * 64 + mi * 16 + (lane >> 2);
        float p0 = 0.f, p1 = 0.f;
#pragma unroll
        for (int ni = 0; ni < 4; ni++) {
            const int col = n0 + wn * 32 + ni * 8 + 2 * (lane & 3);
            float2 bv = *(const float2*)(bias + col);
            float2 v0 = make_float2(c[mi][ni][0] + bv.x, c[mi][ni][1] + bv.y);
            float2 v1 = make_float2(c[mi][ni][2] + bv.x, c[mi][ni][3] + bv.y);
            *(__half2*)(g_Yh + (size_t)row * N1_ + col)       = __floats2half2_rn(v0.x, v0.y);
            *(__half2*)(g_Yh + (size_t)(row + 8) * N1_ + col) = __floats2half2_rn(v1.x, v1.y);
            p0 += v0.x * v0.x + v0.y * v0.y;
            p1 += v1.x * v1.x + v1.y * v1.y;
        }
        p0 += __shfl_xor_sync(0xffffffffu, p0, 1);
        p0 += __shfl_xor_sync(0xffffffffu, p0, 2);
        p1 += __shfl_xor_sync(0xffffffffu, p1, 1);
        p1 += __shfl_xor_sync(0xffffffffu, p1, 2);
        if ((lane & 3) == 0) {
            atomicAdd(&g_rsum[row], p0);
            atomicAdd(&g_rsum[row + 8], p1);
        }
    }
}

// ---------------- kernel 5: GEMM2 + fused T5 RMS-norm + ReLU ----------------
// CTA 64x256x32 (full N2 in CTA), 256 thr (8 warps 2Mx4N, warp 32x64),
// 4-stage cp.async, single barrier per k-tile, 2 CTAs/SM.
__global__ void __launch_bounds__(256, 2)
gemm2_kernel(const float* __restrict__ bias, const float* __restrict__ gw,
             float* __restrict__ out)
{
    extern __shared__ __align__(128) char smem[];
    const int tid  = threadIdx.x;
    const int wid  = tid >> 5;
    const int lane = tid & 31;
    const int wm   = wid & 1;            // 0..1, 32 rows each
    const int wn   = wid >> 1;           // 0..3, 64 cols each
    const int m0 = blockIdx.x * BM2;
    const uint32_t sb = smem_u32(smem);

    const int lrow = tid >> 2;           // 0..63
    const int lch  = tid & 3;
    const uint32_t sRow = (uint32_t)(lrow * LDAB + lch * 16);

    uint32_t aOff[2], wOff[4];
#pragma unroll
    for (int mi = 0; mi < 2; mi++)
        aOff[mi] = (uint32_t)((wm * 32 + mi * 16 + (lane & 15)) * LDAB) + T2_A;
#pragma unroll
    for (int nj = 0; nj < 4; nj++)
        wOff[nj] = (uint32_t)((wn * 64 + nj * 16 + (lane & 15)) * LDAB) + T2_W;

    float c[2][8][4] = {};

#define LOAD_STAGE2(st, kt_) do {                                              \
        uint32_t s = sb + (uint32_t)(st) * STG2 + sRow;                        \
        {                                                                      \
            size_t gA_ = (size_t)(m0 + lrow) * K_ + (kt_) + lch * 8;           \
            cp16(s + T2_A, g_A + gA_);                                         \
        }                                                                      \
        _Pragma("unroll")                                                      \
        for (int i_ = 0; i_ < 4; i_++) {                                       \
            size_t gW_ = (size_t)(lrow + i_ * 64) * K_ + (kt_) + lch * 8;      \
            cp16(s + T2_W + (uint32_t)(i_ * 64 * LDAB), g_W2T + gW_);          \
        }                                                                      \
        CP_COMMIT();                                                           \
    } while (0)

    LOAD_STAGE2(0, 0);
    LOAD_STAGE2(1, BKg);
    LOAD_STAGE2(2, 2 * BKg);

    for (int t = 0; t < NTg; t++) {
        if (t < NTg - 2)       CP_WAIT2();
        else if (t == NTg - 2) CP_WAIT1();
        else                   CP_WAIT0();
        __syncthreads();
        if (t + 3 < NTg) LOAD_STAGE2((t + 3) % NSTAGE, (t + 3) * BKg);

        const uint32_t bufb = sb + (uint32_t)(t % NSTAGE) * STG2;
#pragma unroll
        for (int ks = 0; ks < 2; ks++) {
            const uint32_t kb = bufb + (uint32_t)(ks * 32 + (lane >> 4) * 16);
            uint32_t aw[2][4], bw[4][4];
#pragma unroll
            for (int mi = 0; mi < 2; mi++) LDSM4(aw[mi], kb + aOff[mi]);
#pragma unroll
            for (int nj = 0; nj < 4; nj++) LDSM4(bw[nj], kb + wOff[nj]);
#pragma unroll
            for (int mi = 0; mi < 2; mi++)
#pragma unroll
                for (int nj = 0; nj < 4; nj++) {
                    uint32_t f0[2] = {bw[nj][0], bw[nj][2]};
                    uint32_t f1[2] = {bw[nj][1], bw[nj][3]};
                    MMA_F16(c[mi][2 * nj],     aw[mi], f0);
                    MMA_F16(c[mi][2 * nj + 1], aw[mi], f1);
                }
        }
    }
#undef LOAD_STAGE2

    // ---- fused epilogue: row sumsq (cross-warp via smem), then norm+relu ----
    __syncthreads();                       // all compute done before smem reuse
    float* sp = (float*)smem;              // 64 rows x 4 wn partials
#pragma unroll
    for (int mi = 0; mi < 2; mi++) {
        const int prow = wm * 32 + mi * 16 + (lane >> 2);
        float p0 = 0.f, p1 = 0.f;
#pragma unroll
        for (int ni = 0; ni < 8; ni++) {
            const int col = wn * 64 + ni * 8 + 2 * (lane & 3);
            float2 bv = *(const float2*)(bias + col);
            float2 v0 = make_float2(c[mi][ni][0] + bv.x, c[mi][ni][1] + bv.y);
            float2 v1 = make_float2(c[mi][ni][2] + bv.x, c[mi][ni][3] + bv.y);
            p0 += v0.x * v0.x + v0.y * v0.y;
            p1 += v1.x * v1.x + v1.y * v1.y;
        }
        p0 += __shfl_xor_sync(0xffffffffu, p0, 1);
        p0 += __shfl_xor_sync(0xffffffffu, p0, 2);
        p1 += __shfl_xor_sync(0xffffffffu, p1, 1);
        p1 += __shfl_xor_sync(0xffffffffu, p1, 2);
        if ((lane & 3) == 0) {
            sp[prow * 4 + wn]       = p0;
            sp[(prow + 8) * 4 + wn] = p1;
        }
    }
    __syncthreads();
#pragma unroll
    for (int mi = 0; mi < 2; mi++) {
        const int prow = wm * 32 + mi * 16 + (lane >> 2);
        const float tot0 = sp[prow * 4] + sp[prow * 4 + 1] + sp[prow * 4 + 2] + sp[prow * 4 + 3];
        const float tot1 = sp[(prow + 8) * 4] + sp[(prow + 8) * 4 + 1] +
                           sp[(prow + 8) * 4 + 2] + sp[(prow + 8) * 4 + 3];
        const float r0 = rsqrtf(tot0 * (1.f / (float)N2_) + 1e-12f);
        const float r1 = rsqrtf(tot1 * (1.f / (float)N2_) + 1e-12f);
        const size_t row = (size_t)(m0 + prow);
#pragma unroll
        for (int ni = 0; ni < 8; ni++) {
            const int col = wn * 64 + ni * 8 + 2 * (lane & 3);
            float2 bv = *(const float2*)(bias + col);
            float2 gv = *(const float2*)(gw + col);
            float2 o0, o1;
            o0.x = fmaxf(gv.x * (c[mi][ni][0] + bv.x) * r0, 0.f);
            o0.y = fmaxf(gv.y * (c[mi][ni][1] + bv.y) * r0, 0.f);
            o1.x = fmaxf(gv.x * (c[mi][ni][2] + bv.x) * r1, 0.f);
            o1.y = fmaxf(gv.y * (c[mi][ni][3] + bv.y) * r1, 0.f);
            *(float2*)(out + row * N2_ + col)       = o0;
            *(float2*)(out + (row + 8) * N2_ + col) = o1;
        }
    }
}

// ---------------- launch ----------------------------------------------------
extern "C" void kernel_launch(void* const* d_in, const int* in_sizes, int n_in,
                              void* d_out, int out_size)
{
    (void)in_sizes; (void)n_in; (void)out_size;
    const float* table  = (const float*)d_in[0];
    const float* a_simi = (const float*)d_in[1];
    const float* t_simi = (const float*)d_in[2];
    const float* adj    = (const float*)d_in[3];
    const float* W1     = (const float*)d_in[4];
    const float* b1     = (const float*)d_in[5];
    const float* g1     = (const float*)d_in[6];
    const float* W2     = (const float*)d_in[7];
    const float* b2     = (const float*)d_in[8];
    const float* g2     = (const float*)d_in[9];
    float* out = (float*)d_out;

    static bool attr_set = false;
    if (!attr_set) {
        cudaFuncSetAttribute(gemm1_kernel,
                             cudaFuncAttributeMaxDynamicSharedMemorySize, SMEM_G1);
        cudaFuncSetAttribute(gemm2_kernel,
                             cudaFuncAttributeMaxDynamicSharedMemorySize, SMEM_G2);
        attr_set = true;
    }

    // weight transposes (fp32 -> fp16, coalesced). Destination chosen in-kernel.
    trans_kernel<<<dim3(N1_ / 32, K_ / 32), dim3(32, 8)>>>(W1, 0, N1_);
    trans_kernel<<<dim3(N2_ / 32, K_ / 32), dim3(32, 8)>>>(W2, 1, N2_);

    // layer 1: gather(table) [also zeroes rsum] -> GEMM1(+rsum) -> rfac
    gather_kernel<<<B_ * (S_ / LSL) * KSP, 192>>>(table, a_simi, t_simi, adj, 0, g1);
    gemm1_kernel<<<dim3(N1_ / BN1, M_ / BM1), 256, SMEM_G1>>>(b1);
    rfac_kernel<<<(M_ + 255) / 256, 256>>>();

    // layer 2: gather(norm(Yh)) -> GEMM2 with fused RMS+ReLU
    gather_kernel<<<B_ * (S_ / LSL) * KSP, 192>>>(nullptr, a_simi, t_simi, adj, 1, g1);
    gemm2_kernel<<<M_ / BM2, 256, SMEM_G2>>>(b2, g2, out);
}

// round 15
// speedup vs baseline: 1.0563x; 1.0563x over previous
#include <cuda_runtime.h>
#include <cuda_fp16.h>
#include <cstdint>

// ---------------------------------------------------------------- shapes
#define B_  8
#define S_  96
#define D_  768
#define M_  (B_ * S_ * S_)   // 73728 rows
#define K_  768
#define N1_ 768
#define N2_ 256

// GEMM tiling (mma.sync path, base ISA only)
#define BKg 32               // k per stage
#define NTg (K_ / BKg)       // 24 k-tiles
#define LDAB 80              // bytes per smem row (32 fp16 = 64B + 16B pad)
#define NSTAGE 4
// GEMM1: CTA 128x128, warp 64x32 (2M x 4N)
#define BM1 128
#define BN1 128
#define T1_A 0               // 128 rows * 80B = 10240
#define T1_W 10240
#define STG1 20480
#define SMEM_G1 (NSTAGE * STG1)    // 81920
// GEMM2: CTA 64x256, warp 32x64 (2M x 4N); full N in CTA -> fused RMS
#define BM2 64
#define BN2 256
#define T2_A 0               // 64 rows * 80B = 5120
#define T2_W 5120            // 256 rows * 80B = 20480
#define STG2 25600
#define SMEM_G2 (NSTAGE * STG2)    // 102400
// gather tiling
#define LSL 2                // l-slabs per block (2: low register pressure)
#define KSP 4                // k-range splits -> 8*48*4 = 1536 blocks

// ---------------- scratch (static device globals; no allocations) ----------
// RULE: these symbols are referenced ONLY from device code, never passed as
// kernel arguments from host (host-side shadow address bug, rounds 7 & 10).
static __device__ __half g_Yh[(size_t)M_ * N1_];       // GEMM1 out (pre-norm), fp16
static __device__ float  g_rsum[M_];                   // per-row sum of squares
static __device__ float  g_rfac[M_];                   // rsqrt factors
static __device__ __half g_A[(size_t)M_ * K_];         // gather out, fp16
static __device__ __half g_W1T[(size_t)N1_ * K_];      // W^T, k-contiguous, fp16
static __device__ __half g_W2T[(size_t)N2_ * K_];

// ---------------------------------------------------------------- helpers
__device__ __forceinline__ uint32_t smem_u32(const void* p) {
    uint32_t a;
    asm("{ .reg .u64 t; cvta.to.shared.u64 t, %1; cvt.u32.u64 %0, t; }" : "=r"(a) : "l"(p));
    return a;
}

__device__ __forceinline__ void cp16(uint32_t s, const void* g) {
    asm volatile("cp.async.cg.shared.global [%0], [%1], 16;" :: "r"(s), "l"(g));
}
#define CP_COMMIT() asm volatile("cp.async.commit_group;" ::: "memory")
#define CP_WAIT2()  asm volatile("cp.async.wait_group 2;" ::: "memory")
#define CP_WAIT1()  asm volatile("cp.async.wait_group 1;" ::: "memory")
#define CP_WAIT0()  asm volatile("cp.async.wait_group 0;" ::: "memory")

#define LDSM4(r, addr) \
    asm volatile("ldmatrix.sync.aligned.m8n8.x4.shared.b16 {%0,%1,%2,%3}, [%4];" \
        : "=r"((r)[0]), "=r"((r)[1]), "=r"((r)[2]), "=r"((r)[3]) : "r"(addr))

#define MMA_F16(Cv, Av, Bv) asm volatile( \
    "mma.sync.aligned.m16n8k16.row.col.f32.f16.f16.f32 " \
    "{%0,%1,%2,%3}, {%4,%5,%6,%7}, {%8,%9}, {%0,%1,%2,%3};\n" \
    : "+f"((Cv)[0]), "+f"((Cv)[1]), "+f"((Cv)[2]), "+f"((Cv)[3]) \
    : "r"((Av)[0]), "r"((Av)[1]), "r"((Av)[2]), "r"((Av)[3]), \
      "r"((Bv)[0]), "r"((Bv)[1]))

// ---------------- kernel 1: coalesced W -> W^T fp16 transpose ---------------
// Destination selected INSIDE device code (which=0 -> g_W1T, 1 -> g_W2T).
__global__ void trans_kernel(const float* __restrict__ W, int which, int N)
{
    __half* __restrict__ WT = which ? g_W2T : g_W1T;
    __shared__ float tile[32][33];
    const int n0 = blockIdx.x * 32, k0 = blockIdx.y * 32;
    const int tx = threadIdx.x, ty = threadIdx.y;
#pragma unroll
    for (int r = 0; r < 4; r++)
        tile[ty + 8 * r][tx] = W[(size_t)(k0 + ty + 8 * r) * N + n0 + tx];
    __syncthreads();
#pragma unroll
    for (int r = 0; r < 4; r++)
        WT[(size_t)(n0 + ty + 8 * r) * K_ + k0 + tx] = __float2half(tile[tx][ty + 8 * r]);
}

// ---------------- kernel 2: 2-slab register-tiled gather stencil ------------
__device__ __forceinline__ void fma4(float4& r, float s, const float4 v) {
    r.x += s * v.x; r.y += s * v.y; r.z += s * v.z; r.w += s * v.w;
}

__device__ __forceinline__ float4 loadrow(const float* __restrict__ hf, int src, int t,
                                          int use_norm, const float4 g4)
{
    float4 v;
    if (hf) {
        v = ((const float4*)(hf + (size_t)src * D_))[t];
    } else {
        uint2 u = *((const uint2*)(g_Yh + (size_t)src * D_) + t);
        __half2 a = *(__half2*)&u.x;
        __half2 b = *(__half2*)&u.y;
        v.x = __half2float(a.x); v.y = __half2float(a.y);
        v.z = __half2float(b.x); v.w = __half2float(b.y);
    }
    if (use_norm) {
        const float r = g_rfac[src];
        v.x = fmaxf(g4.x * v.x * r, 0.f);
        v.y = fmaxf(g4.y * v.y * r, 0.f);
        v.z = fmaxf(g4.z * v.z * r, 0.f);
        v.w = fmaxf(g4.w * v.w * r, 0.f);
    }
    return v;
}

// One block = 2 adjacent l-slabs x one quarter of the k-range. Each slab has a
// prev/cur/nxt register rotation (own rows read once); the interior up/down
// neighbor is the adjacent rotation's `cur`; only slabs l0-1 and l0+2 are
// loaded per k-step. Reads per output: 2.0 (vs 3.0 single-slab).
__global__ void gather_kernel(const float* __restrict__ table,
                              const float* __restrict__ a_simi,
                              const float* __restrict__ t_simi,
                              const float* __restrict__ adj,
                              int use_norm, const float* __restrict__ gw)
{
    const int kq  = blockIdx.x & (KSP - 1);
    const int bl2 = blockIdx.x / KSP;                  // b*(S/LSL) + l0/LSL
    const int b  = bl2 / (S_ / LSL);
    const int l0 = (bl2 % (S_ / LSL)) * LSL;
    const int t = threadIdx.x;                         // 0..191 (float4 over D)
    const int k0 = kq * (S_ / KSP);
    const int k1 = k0 + (S_ / KSP);

    float4 g4 = make_float4(1.f, 1.f, 1.f, 1.f);
    if (use_norm) g4 = ((const float4*)gw)[t];

    const float4 zero4 = make_float4(0.f, 0.f, 0.f, 0.f);

    int   base[LSL];
    float au[LSL], ad[LSL];
    float4 diag[LSL], prev[LSL], cur[LSL], nxt[LSL];
#pragma unroll
    for (int j = 0; j < LSL; j++) {
        const int l = l0 + j;
        base[j] = (b * S_ + l) * S_;
        au[j] = (l > 0)      ? a_simi[b * S_ + l - 1] : 0.f;
        ad[j] = (l < S_ - 1) ? a_simi[b * S_ + l + 1] : 0.f;
        diag[j] = loadrow(table, base[j] + l, t, use_norm, g4);
        prev[j] = (k0 > 0) ? loadrow(table, base[j] + k0 - 1, t, use_norm, g4) : zero4;
        cur[j]  = loadrow(table, base[j] + k0, t, use_norm, g4);
        nxt[j]  = loadrow(table, base[j] + k0 + 1, t, use_norm, g4);
    }

    for (int k = k0; k < k1; k++) {
        // external boundary neighbors (slabs l0-1 and l0+LSL)
        const float4 up = (l0 > 0)        ? loadrow(table, base[0] - S_ + k, t, use_norm, g4) : zero4;
        const float4 dn = (l0 + LSL < S_) ? loadrow(table, base[LSL - 1] + S_ + k, t, use_norm, g4) : zero4;
        const float tl = (k > 0)      ? t_simi[b * S_ + k - 1] : 0.f;
        const float tr = (k < S_ - 1) ? t_simi[b * S_ + k + 1] : 0.f;

#pragma unroll
        for (int j = 0; j < LSL; j++) {
            const int idx = base[j] + k;
            const float adjv = adj[idx];
            float4 r;
            r.x = 2.f * cur[j].x + adjv * diag[j].x;
            r.y = 2.f * cur[j].y + adjv * diag[j].y;
            r.z = 2.f * cur[j].z + adjv * diag[j].z;
            r.w = 2.f * cur[j].w + adjv * diag[j].w;
            if (k > 0)      fma4(r, tl, prev[j]);
            if (k < S_ - 1) fma4(r, tr, nxt[j]);
            fma4(r, au[j], (j == 0)       ? up : cur[j - 1]);
            fma4(r, ad[j], (j == LSL - 1) ? dn : cur[j + 1]);

            __half2 v01, v23;
            v01.x = __float2half(r.x); v01.y = __float2half(r.y);
            v23.x = __float2half(r.z); v23.y = __float2half(r.w);
            __half2* pa = (__half2*)(g_A + (size_t)idx * D_) + 2 * t;
            pa[0] = v01;
            pa[1] = v23;
            if (!use_norm && t == 0) g_rsum[idx] = 0.f;
        }
        // rotate both slabs
#pragma unroll
        for (int j = 0; j < LSL; j++) {
            prev[j] = cur[j]; cur[j] = nxt[j];
            nxt[j] = (k + 2 < S_) ? loadrow(table, base[j] + k + 2, t, use_norm, g4) : zero4;
        }
    }
}

// ---------------- kernel 3: rfac = rsqrt(rsum/D + eps) ----------------------
__global__ void rfac_kernel()
{
    int i = blockIdx.x * blockDim.x + threadIdx.x;
    if (i < M_) g_rfac[i] = rsqrtf(g_rsum[i] * (1.f / (float)N1_) + 1e-12f);
}

// ---------------- kernel 4: GEMM1  Yh = fp16(A@W1^T + b1), +rsum ------------
// CTA 128x128x32, 256 thr (8 warps 2Mx4N, warp 64x32), 4-stage cp.async,
// single barrier per k-tile, 2 CTAs/SM.
__global__ void __launch_bounds__(256, 2)
gemm1_kernel(const float* __restrict__ bias)
{
    extern __shared__ __align__(128) char smem[];
    const int tid  = threadIdx.x;
    const int wid  = tid >> 5;
    const int lane = tid & 31;
    const int wm   = wid & 1;            // 0..1, 64 rows each
    const int wn   = wid >> 1;           // 0..3, 32 cols each
    const int m0 = blockIdx.y * BM1;
    const int n0 = blockIdx.x * BN1;
    const uint32_t sb = smem_u32(smem);

    const int lrow = tid >> 2;           // 0..63
    const int lch  = tid & 3;
    const uint32_t sRow = (uint32_t)(lrow * LDAB + lch * 16);

    uint32_t aOff[4], wOff[2];
#pragma unroll
    for (int mi = 0; mi < 4; mi++)
        aOff[mi] = (uint32_t)((wm * 64 + mi * 16 + (lane & 15)) * LDAB) + T1_A;
#pragma unroll
    for (int nj = 0; nj < 2; nj++)
        wOff[nj] = (uint32_t)((wn * 32 + nj * 16 + (lane & 15)) * LDAB) + T1_W;

    float c[4][4][4] = {};

#define LOAD_STAGE1(st, kt_) do {                                              \
        uint32_t s = sb + (uint32_t)(st) * STG1 + sRow;                        \
        _Pragma("unroll")                                                      \
        for (int i_ = 0; i_ < 2; i_++) {                                       \
            size_t gA_ = (size_t)(m0 + lrow + i_ * 64) * K_ + (kt_) + lch * 8; \
            cp16(s + T1_A + (uint32_t)(i_ * 64 * LDAB), g_A + gA_);            \
            size_t gW_ = (size_t)(n0 + lrow + i_ * 64) * K_ + (kt_) + lch * 8; \
            cp16(s + T1_W + (uint32_t)(i_ * 64 * LDAB), g_W1T + gW_);          \
        }                                                                      \
        CP_COMMIT();                                                           \
    } while (0)

    LOAD_STAGE1(0, 0);
    LOAD_STAGE1(1, BKg);
    LOAD_STAGE1(2, 2 * BKg);

    for (int t = 0; t < NTg; t++) {
        if (t < NTg - 2)       CP_WAIT2();
        else if (t == NTg - 2) CP_WAIT1();
        else                   CP_WAIT0();
        __syncthreads();
        if (t + 3 < NTg) LOAD_STAGE1((t + 3) % NSTAGE, (t + 3) * BKg);

        const uint32_t bufb = sb + (uint32_t)(t % NSTAGE) * STG1;
#pragma unroll
        for (int ks = 0; ks < 2; ks++) {
            const uint32_t kb = bufb + (uint32_t)(ks * 32 + (lane >> 4) * 16);
            uint32_t aw[4][4], bw[2][4];
#pragma unroll
            for (int mi = 0; mi < 4; mi++) LDSM4(aw[mi], kb + aOff[mi]);
#pragma unroll
            for (int nj = 0; nj < 2; nj++) LDSM4(bw[nj], kb + wOff[nj]);
#pragma unroll
            for (int mi = 0; mi < 4; mi++)
#pragma unroll
                for (int nj = 0; nj < 2; nj++) {
                    uint32_t f0[2] = {bw[nj][0], bw[nj][2]};
                    uint32_t f1[2] = {bw[nj][1], bw[nj][3]};
                    MMA_F16(c[mi][2 * nj],     aw[mi], f0);
                    MMA_F16(c[mi][2 * nj + 1], aw[mi], f1);
                }
        }
    }
#undef LOAD_STAGE1

    // epilogue: + bias, fp16 store, per-row sumsq via atomics
#pragma unroll
    for (int mi = 0; mi < 4; mi++) {
        const int row = m0 + wm * 64 + mi * 16 + (lane >> 2);
        float p0 = 0.f, p1 = 0.f;
#pragma unroll
        for (int ni = 0; ni < 4; ni++) {
            const int col = n0 + wn * 32 + ni * 8 + 2 * (lane & 3);
            float2 bv = *(const float2*)(bias + col);
            float2 v0 = make_float2(c[mi][ni][0] + bv.x, c[mi][ni][1] + bv.y);
            float2 v1 = make_float2(c[mi][ni][2] + bv.x, c[mi][ni][3] + bv.y);
            *(__half2*)(g_Yh + (size_t)row * N1_ + col)       = __floats2half2_rn(v0.x, v0.y);
            *(__half2*)(g_Yh + (size_t)(row + 8) * N1_ + col) = __floats2half2_rn(v1.x, v1.y);
            p0 += v0.x * v0.x + v0.y * v0.y;
            p1 += v1.x * v1.x + v1.y * v1.y;
        }
        p0 += __shfl_xor_sync(0xffffffffu, p0, 1);
        p0 += __shfl_xor_sync(0xffffffffu, p0, 2);
        p1 += __shfl_xor_sync(0xffffffffu, p1, 1);
        p1 += __shfl_xor_sync(0xffffffffu, p1, 2);
        if ((lane & 3) == 0) {
            atomicAdd(&g_rsum[row], p0);
            atomicAdd(&g_rsum[row + 8], p1);
        }
    }
}

// ---------------- kernel 5: GEMM2 + fused T5 RMS-norm + ReLU ----------------
// CTA 64x256x32 (full N2 in CTA), 256 thr (8 warps 2Mx4N, warp 32x64),
// 4-stage cp.async, single barrier per k-tile, 2 CTAs/SM.
__global__ void __launch_bounds__(256, 2)
gemm2_kernel(const float* __restrict__ bias, const float* __restrict__ gw,
             float* __restrict__ out)
{
    extern __shared__ __align__(128) char smem[];
    const int tid  = threadIdx.x;
    const int wid  = tid >> 5;
    const int lane = tid & 31;
    const int wm   = wid & 1;            // 0..1, 32 rows each
    const int wn   = wid >> 1;           // 0..3, 64 cols each
    const int m0 = blockIdx.x * BM2;
    const uint32_t sb = smem_u32(smem);

    const int lrow = tid >> 2;           // 0..63
    const int lch  = tid & 3;
    const uint32_t sRow = (uint32_t)(lrow * LDAB + lch * 16);

    uint32_t aOff[2], wOff[4];
#pragma unroll
    for (int mi = 0; mi < 2; mi++)
        aOff[mi] = (uint32_t)((wm * 32 + mi * 16 + (lane & 15)) * LDAB) + T2_A;
#pragma unroll
    for (int nj = 0; nj < 4; nj++)
        wOff[nj] = (uint32_t)((wn * 64 + nj * 16 + (lane & 15)) * LDAB) + T2_W;

    float c[2][8][4] = {};

#define LOAD_STAGE2(st, kt_) do {                                              \
        uint32_t s = sb + (uint32_t)(st) * STG2 + sRow;                        \
        {                                                                      \
            size_t gA_ = (size_t)(m0 + lrow) * K_ + (kt_) + lch * 8;           \
            cp16(s + T2_A, g_A + gA_);                                         \
        }                                                                      \
        _Pragma("unroll")                                                      \
        for (int i_ = 0; i_ < 4; i_++) {                                       \
            size_t gW_ = (size_t)(lrow + i_ * 64) * K_ + (kt_) + lch * 8;      \
            cp16(s + T2_W + (uint32_t)(i_ * 64 * LDAB), g_W2T + gW_);          \
        }                                                                      \
        CP_COMMIT();                                                           \
    } while (0)

    LOAD_STAGE2(0, 0);
    LOAD_STAGE2(1, BKg);
    LOAD_STAGE2(2, 2 * BKg);

    for (int t = 0; t < NTg; t++) {
        if (t < NTg - 2)       CP_WAIT2();
        else if (t == NTg - 2) CP_WAIT1();
        else                   CP_WAIT0();
        __syncthreads();
        if (t + 3 < NTg) LOAD_STAGE2((t + 3) % NSTAGE, (t + 3) * BKg);

        const uint32_t bufb = sb + (uint32_t)(t % NSTAGE) * STG2;
#pragma unroll
        for (int ks = 0; ks < 2; ks++) {
            const uint32_t kb = bufb + (uint32_t)(ks * 32 + (lane >> 4) * 16);
            uint32_t aw[2][4], bw[4][4];
#pragma unroll
            for (int mi = 0; mi < 2; mi++) LDSM4(aw[mi], kb + aOff[mi]);
#pragma unroll
            for (int nj = 0; nj < 4; nj++) LDSM4(bw[nj], kb + wOff[nj]);
#pragma unroll
            for (int mi = 0; mi < 2; mi++)
#pragma unroll
                for (int nj = 0; nj < 4; nj++) {
                    uint32_t f0[2] = {bw[nj][0], bw[nj][2]};
                    uint32_t f1[2] = {bw[nj][1], bw[nj][3]};
                    MMA_F16(c[mi][2 * nj],     aw[mi], f0);
                    MMA_F16(c[mi][2 * nj + 1], aw[mi], f1);
                }
        }
    }
#undef LOAD_STAGE2

    // ---- fused epilogue: row sumsq (cross-warp via smem), then norm+relu ----
    __syncthreads();                       // all compute done before smem reuse
    float* sp = (float*)smem;              // 64 rows x 4 wn partials
#pragma unroll
    for (int mi = 0; mi < 2; mi++) {
        const int prow = wm * 32 + mi * 16 + (lane >> 2);
        float p0 = 0.f, p1 = 0.f;
#pragma unroll
        for (int ni = 0; ni < 8; ni++) {
            const int col = wn * 64 + ni * 8 + 2 * (lane & 3);
            float2 bv = *(const float2*)(bias + col);
            float2 v0 = make_float2(c[mi][ni][0] + bv.x, c[mi][ni][1] + bv.y);
            float2 v1 = make_float2(c[mi][ni][2] + bv.x, c[mi][ni][3] + bv.y);
            p0 += v0.x * v0.x + v0.y * v0.y;
            p1 += v1.x * v1.x + v1.y * v1.y;
        }
        p0 += __shfl_xor_sync(0xffffffffu, p0, 1);
        p0 += __shfl_xor_sync(0xffffffffu, p0, 2);
        p1 += __shfl_xor_sync(0xffffffffu, p1, 1);
        p1 += __shfl_xor_sync(0xffffffffu, p1, 2);
        if ((lane & 3) == 0) {
            sp[prow * 4 + wn]       = p0;
            sp[(prow + 8) * 4 + wn] = p1;
        }
    }
    __syncthreads();
#pragma unroll
    for (int mi = 0; mi < 2; mi++) {
        const int prow = wm * 32 + mi * 16 + (lane >> 2);
        const float tot0 = sp[prow * 4] + sp[prow * 4 + 1] + sp[prow * 4 + 2] + sp[prow * 4 + 3];
        const float tot1 = sp[(prow + 8) * 4] + sp[(prow + 8) * 4 + 1] +
                           sp[(prow + 8) * 4 + 2] + sp[(prow + 8) * 4 + 3];
        const float r0 = rsqrtf(tot0 * (1.f / (float)N2_) + 1e-12f);
        const float r1 = rsqrtf(tot1 * (1.f / (float)N2_) + 1e-12f);
        const size_t row = (size_t)(m0 + prow);
#pragma unroll
        for (int ni = 0; ni < 8; ni++) {
            const int col = wn * 64 + ni * 8 + 2 * (lane & 3);
            float2 bv = *(const float2*)(bias + col);
            float2 gv = *(const float2*)(gw + col);
            float2 o0, o1;
            o0.x = fmaxf(gv.x * (c[mi][ni][0] + bv.x) * r0, 0.f);
            o0.y = fmaxf(gv.y * (c[mi][ni][1] + bv.y) * r0, 0.f);
            o1.x = fmaxf(gv.x * (c[mi][ni][2] + bv.x) * r1, 0.f);
            o1.y = fmaxf(gv.y * (c[mi][ni][3] + bv.y) * r1, 0.f);
            *(float2*)(out + row * N2_ + col)       = o0;
            *(float2*)(out + (row + 8) * N2_ + col) = o1;
        }
    }
}

// ---------------- launch ----------------------------------------------------
extern "C" void kernel_launch(void* const* d_in, const int* in_sizes, int n_in,
                              void* d_out, int out_size)
{
    (void)in_sizes; (void)n_in; (void)out_size;
    const float* table  = (const float*)d_in[0];
    const float* a_simi = (const float*)d_in[1];
    const float* t_simi = (const float*)d_in[2];
    const float* adj    = (const float*)d_in[3];
    const float* W1     = (const float*)d_in[4];
    const float* b1     = (const float*)d_in[5];
    const float* g1     = (const float*)d_in[6];
    const float* W2     = (const float*)d_in[7];
    const float* b2     = (const float*)d_in[8];
    const float* g2     = (const float*)d_in[9];
    float* out = (float*)d_out;

    static bool attr_set = false;
    if (!attr_set) {
        cudaFuncSetAttribute(gemm1_kernel,
                             cudaFuncAttributeMaxDynamicSharedMemorySize, SMEM_G1);
        cudaFuncSetAttribute(gemm2_kernel,
                             cudaFuncAttributeMaxDynamicSharedMemorySize, SMEM_G2);
        attr_set = true;
    }

    // weight transposes (fp32 -> fp16, coalesced). Destination chosen in-kernel.
    trans_kernel<<<dim3(N1_ / 32, K_ / 32), dim3(32, 8)>>>(W1, 0, N1_);
    trans_kernel<<<dim3(N2_ / 32, K_ / 32), dim3(32, 8)>>>(W2, 1, N2_);

    // layer 1: gather(table) [also zeroes rsum] -> GEMM1(+rsum) -> rfac
    gather_kernel<<<B_ * (S_ / LSL) * KSP, 192>>>(table, a_simi, t_simi, adj, 0, g1);
    gemm1_kernel<<<dim3(N1_ / BN1, M_ / BM1), 256, SMEM_G1>>>(b1);
    rfac_kernel<<<(M_ + 255) / 256, 256>>>();

    // layer 2: gather(norm(Yh)) -> GEMM2 with fused RMS+ReLU
    gather_kernel<<<B_ * (S_ / LSL) * KSP, 192>>>(nullptr, a_simi, t_simi, adj, 1, g1);
    gemm2_kernel<<<M_ / BM2, 256, SMEM_G2>>>(b2, g2, out);
}